// round 10
// baseline (speedup 1.0000x reference)
#include <cuda_runtime.h>
#include <cuda_bf16.h>
#include <cuda_fp16.h>

// FeaturesLinear: out[b,:] = sum_{t in segment b} user_W[fid[t],:] * rating_W[ridx[t],:]
//                           + item_W[item_ids[b],:] + bias
// Two-kernel plan (traffic reduction; kernel was pinned at the ~6.3 KB/cyc LTS
// cap on ~444 MB):
//   K1: convert user_W fp32 -> packed fp16 mirror in static device scratch
//       (77 MB one-shot traffic per launch).
//   K2: the proven 35.3us gather formulation, but gathering 256B fp16 rows
//       instead of 512B fp32 rows (210 MB instead of 419 MB). Accumulation
//       stays fp32; only the gathered operand is rounded (norm rel_err ~1e-4).
// Total ~311 MB vs 444 MB.

#define HIST 50
#define DVEC 32            // 128 dims / 4 (float4 / 2xhalf2-pair per lane)
#define WARPS_PER_BLOCK 4
#define THREADS (WARPS_PER_BLOCK * 32)
#define NU 100001          // NUM_ITEMS + 1
#define NU4 (NU * 32)      // float4 count of user_W

// fp16 mirror of user_W: NU rows x 128 halves = 25.6 MB, viewed as uint2
// (4 halves) per lane. Static device scratch (no allocation).
__device__ __align__(16) uint2 g_uW_h[NU * 32];

__global__ __launch_bounds__(256)
void convert_userW_kernel(const float4* __restrict__ userW)
{
    const int stride = gridDim.x * blockDim.x;
    for (int i = blockIdx.x * blockDim.x + threadIdx.x; i < NU4; i += stride) {
        const float4 v = __ldg(&userW[i]);
        const __half2 a = __floats2half2_rn(v.x, v.y);
        const __half2 b = __floats2half2_rn(v.z, v.w);
        uint2 o;
        o.x = *reinterpret_cast<const unsigned*>(&a);
        o.y = *reinterpret_cast<const unsigned*>(&b);
        g_uW_h[i] = o;
    }
}

__global__ __launch_bounds__(THREADS, 16)
void features_linear_kernel(const int*    __restrict__ fids,      // [T]
                            const float*  __restrict__ ratings,   // [T]
                            const int*    __restrict__ segs,      // [T]
                            const int*    __restrict__ item_ids,  // [B]
                            const float4* __restrict__ ratingW,   // [10, 32]
                            const float4* __restrict__ itemW,     // [Ni, 32]
                            const float4* __restrict__ bias,      // [32]
                            float4*       __restrict__ out,       // [B, 32]
                            int batch)
{
    __shared__ float4 s_rw[10 * DVEC];   // 5 KB: full rating_W table
    __shared__ float4 s_bias[DVEC];

    for (int i = threadIdx.x; i < 10 * DVEC; i += THREADS) s_rw[i] = ratingW[i];
    if (threadIdx.x < DVEC) s_bias[threadIdx.x] = bias[threadIdx.x];
    __syncthreads();

    const int gwarp = (blockIdx.x * THREADS + threadIdx.x) >> 5;
    const int lane  = threadIdx.x & 31;
    if (gwarp >= batch) return;

    const int base = gwarp * HIST;

    // ---- Front-batched loads: indices + epilogue gather issued before any
    // dependent compute so the LSU queue is deep from cycle ~0. ----
    int   fid0 = __ldg(&fids[base + lane]);
    float r0   = __ldg(&ratings[base + lane]);
    const bool lane2 = (lane < HIST - 32);
    int   fid1 = 0;
    float r1   = 0.0f;
    if (lane2) {
        fid1 = __ldg(&fids[base + 32 + lane]);
        r1   = __ldg(&ratings[base + 32 + lane]);
    }
    const int row = __ldg(&segs[base]);                                  // output row
    const float4 it = __ldg(&itemW[(size_t)__ldg(&item_ids[row]) * DVEC + lane]);

    int rx0 = __float2int_rn((r0 - 0.5f) * 2.0f);
    rx0 = min(max(rx0, 0), 9);
    int rx1 = 15;                       // sentinel: never matches any bucket
    if (lane2) {
        rx1 = __float2int_rn((r1 - 0.5f) * 2.0f);
        rx1 = min(max(rx1, 0), 9);
    }

    const uint2* __restrict__ uWh = g_uW_h;
    float4 acc = make_float4(0.f, 0.f, 0.f, 0.f);

    #pragma unroll
    for (int rx = 0; rx < 10; rx++) {
        unsigned m0 = __ballot_sync(0xffffffffu, rx0 == rx);
        unsigned m1 = __ballot_sync(0xffffffffu, rx1 == rx);

        float4 p = make_float4(0.f, 0.f, 0.f, 0.f);
        while (m0) {
            const int i = __ffs(m0) - 1;
            m0 &= m0 - 1;
            const int fid = __shfl_sync(0xffffffffu, fid0, i);
            const uint2 raw = __ldg(&uWh[((size_t)fid << 5) + lane]);
            const float2 f01 = __half22float2(*reinterpret_cast<const __half2*>(&raw.x));
            const float2 f23 = __half22float2(*reinterpret_cast<const __half2*>(&raw.y));
            p.x += f01.x; p.y += f01.y; p.z += f23.x; p.w += f23.y;
        }
        while (m1) {
            const int i = __ffs(m1) - 1;
            m1 &= m1 - 1;
            const int fid = __shfl_sync(0xffffffffu, fid1, i);
            const uint2 raw = __ldg(&uWh[((size_t)fid << 5) + lane]);
            const float2 f01 = __half22float2(*reinterpret_cast<const __half2*>(&raw.x));
            const float2 f23 = __half22float2(*reinterpret_cast<const __half2*>(&raw.y));
            p.x += f01.x; p.y += f01.y; p.z += f23.x; p.w += f23.y;
        }

        const float4 s = s_rw[rx * DVEC + lane];
        acc.x = fmaf(p.x, s.x, acc.x);
        acc.y = fmaf(p.y, s.y, acc.y);
        acc.z = fmaf(p.z, s.z, acc.z);
        acc.w = fmaf(p.w, s.w, acc.w);
    }

    const float4 bz = s_bias[lane];
    float4 o;
    o.x = acc.x + it.x + bz.x;
    o.y = acc.y + it.y + bz.y;
    o.z = acc.z + it.z + bz.z;
    o.w = acc.w + it.w + bz.w;
    out[(size_t)row * DVEC + lane] = o;
}

extern "C" void kernel_launch(void* const* d_in, const int* in_sizes, int n_in,
                              void* d_out, int out_size)
{
    const int*    fids     = (const int*)   d_in[0];
    const float*  ratings  = (const float*) d_in[1];
    const int*    segs     = (const int*)   d_in[2];
    const int*    item_ids = (const int*)   d_in[3];
    const float4* userW    = (const float4*)d_in[4];
    const float4* ratingW  = (const float4*)d_in[5];
    const float4* itemW    = (const float4*)d_in[6];
    const float4* bias     = (const float4*)d_in[7];
    float4*       out      = (float4*)      d_out;

    const int batch  = in_sizes[3];                 // item_ids count
    const int blocks = (batch + WARPS_PER_BLOCK - 1) / WARPS_PER_BLOCK;

    // K1: refresh the fp16 mirror (userW could change between launches).
    convert_userW_kernel<<<2048, 256>>>(userW);

    // K2: gather/accumulate from the fp16 mirror.
    features_linear_kernel<<<blocks, THREADS>>>(
        fids, ratings, segs, item_ids, ratingW, itemW, bias, out, batch);
}

// round 11
// speedup vs baseline: 1.2053x; 1.2053x over previous
#include <cuda_runtime.h>
#include <cuda_bf16.h>

// FeaturesLinear: out[b,:] = sum_{t in segment b} user_W[fid[t],:] * rating_W[ridx[t],:]
//                           + item_W[item_ids[b],:] + bias
// Segments = contiguous runs of HIST=50. Group-by-rating (ballot over 10
// buckets), raw-row accumulation per bucket, one FMA per bucket.
// R10 finding: fp16 mirror at half the bytes ran the SAME 38us as fp32 ->
// the kernel has an intra-SM per-gather floor alongside the LTS byte cap.
// This revision attacks that floor: dual-pop (two gathers per scan iteration,
// two independent accumulator chains -> paired LDG.128 issue, shorter FADD
// chains). launch_bounds relaxed to 12 blocks/SM so the extra live float4
// doesn't spill (regs ~40 < 42 budget).

#define HIST 50
#define DVEC 32            // 128 dims / 4 (float4 per lane)
#define WARPS_PER_BLOCK 4
#define THREADS (WARPS_PER_BLOCK * 32)

__global__ __launch_bounds__(THREADS, 12)
void features_linear_kernel(const int*    __restrict__ fids,      // [T]
                            const float*  __restrict__ ratings,   // [T]
                            const int*    __restrict__ segs,      // [T]
                            const int*    __restrict__ item_ids,  // [B]
                            const float4* __restrict__ userW,     // [Nu, 32]
                            const float4* __restrict__ ratingW,   // [10, 32]
                            const float4* __restrict__ itemW,     // [Ni, 32]
                            const float4* __restrict__ bias,      // [32]
                            float4*       __restrict__ out,       // [B, 32]
                            int batch)
{
    __shared__ float4 s_rw[10 * DVEC];   // 5 KB: full rating_W table
    __shared__ float4 s_bias[DVEC];

    for (int i = threadIdx.x; i < 10 * DVEC; i += THREADS) s_rw[i] = ratingW[i];
    if (threadIdx.x < DVEC) s_bias[threadIdx.x] = bias[threadIdx.x];
    __syncthreads();

    const int gwarp = (blockIdx.x * THREADS + threadIdx.x) >> 5;
    const int lane  = threadIdx.x & 31;
    if (gwarp >= batch) return;

    const int base = gwarp * HIST;

    // ---- Front-batched loads: indices + epilogue gather issued before any
    // dependent compute so the LSU queue is deep from cycle ~0. ----
    int   fid0 = __ldg(&fids[base + lane]);
    float r0   = __ldg(&ratings[base + lane]);
    const bool lane2 = (lane < HIST - 32);
    int   fid1 = 0;
    float r1   = 0.0f;
    if (lane2) {
        fid1 = __ldg(&fids[base + 32 + lane]);
        r1   = __ldg(&ratings[base + 32 + lane]);
    }
    const int row = __ldg(&segs[base]);                                  // output row
    const float4 it = __ldg(&itemW[(size_t)__ldg(&item_ids[row]) * DVEC + lane]);

    int rx0 = __float2int_rn((r0 - 0.5f) * 2.0f);
    rx0 = min(max(rx0, 0), 9);
    int rx1 = 15;                       // sentinel: never matches any bucket
    if (lane2) {
        rx1 = __float2int_rn((r1 - 0.5f) * 2.0f);
        rx1 = min(max(rx1, 0), 9);
    }

    float4 acc = make_float4(0.f, 0.f, 0.f, 0.f);

    #pragma unroll
    for (int rx = 0; rx < 10; rx++) {
        unsigned m0 = __ballot_sync(0xffffffffu, rx0 == rx);
        unsigned m1 = __ballot_sync(0xffffffffu, rx1 == rx);

        float4 pa = make_float4(0.f, 0.f, 0.f, 0.f);
        float4 pb = make_float4(0.f, 0.f, 0.f, 0.f);

        // Dual-pop: two gathers per iteration, independent accumulator chains.
        // Mask values are warp-uniform (ballot), so the branches are uniform.
        while (m0) {
            const int i = __ffs(m0) - 1;
            m0 &= m0 - 1;
            const int fa = __shfl_sync(0xffffffffu, fid0, i);
            if (m0) {
                const int j = __ffs(m0) - 1;
                m0 &= m0 - 1;
                const int fb = __shfl_sync(0xffffffffu, fid0, j);
                const float4 ua = __ldg(&userW[(size_t)fa * DVEC + lane]);
                const float4 ub = __ldg(&userW[(size_t)fb * DVEC + lane]);
                pa.x += ua.x; pa.y += ua.y; pa.z += ua.z; pa.w += ua.w;
                pb.x += ub.x; pb.y += ub.y; pb.z += ub.z; pb.w += ub.w;
            } else {
                const float4 ua = __ldg(&userW[(size_t)fa * DVEC + lane]);
                pa.x += ua.x; pa.y += ua.y; pa.z += ua.z; pa.w += ua.w;
            }
        }
        while (m1) {
            const int i = __ffs(m1) - 1;
            m1 &= m1 - 1;
            const int fa = __shfl_sync(0xffffffffu, fid1, i);
            if (m1) {
                const int j = __ffs(m1) - 1;
                m1 &= m1 - 1;
                const int fb = __shfl_sync(0xffffffffu, fid1, j);
                const float4 ua = __ldg(&userW[(size_t)fa * DVEC + lane]);
                const float4 ub = __ldg(&userW[(size_t)fb * DVEC + lane]);
                pa.x += ua.x; pa.y += ua.y; pa.z += ua.z; pa.w += ua.w;
                pb.x += ub.x; pb.y += ub.y; pb.z += ub.z; pb.w += ub.w;
            } else {
                const float4 ua = __ldg(&userW[(size_t)fa * DVEC + lane]);
                pa.x += ua.x; pa.y += ua.y; pa.z += ua.z; pa.w += ua.w;
            }
        }

        const float4 s = s_rw[rx * DVEC + lane];
        acc.x = fmaf(pa.x + pb.x, s.x, acc.x);
        acc.y = fmaf(pa.y + pb.y, s.y, acc.y);
        acc.z = fmaf(pa.z + pb.z, s.z, acc.z);
        acc.w = fmaf(pa.w + pb.w, s.w, acc.w);
    }

    const float4 bz = s_bias[lane];
    float4 o;
    o.x = acc.x + it.x + bz.x;
    o.y = acc.y + it.y + bz.y;
    o.z = acc.z + it.z + bz.z;
    o.w = acc.w + it.w + bz.w;
    out[(size_t)row * DVEC + lane] = o;
}

extern "C" void kernel_launch(void* const* d_in, const int* in_sizes, int n_in,
                              void* d_out, int out_size)
{
    const int*    fids     = (const int*)   d_in[0];
    const float*  ratings  = (const float*) d_in[1];
    const int*    segs     = (const int*)   d_in[2];
    const int*    item_ids = (const int*)   d_in[3];
    const float4* userW    = (const float4*)d_in[4];
    const float4* ratingW  = (const float4*)d_in[5];
    const float4* itemW    = (const float4*)d_in[6];
    const float4* bias     = (const float4*)d_in[7];
    float4*       out      = (float4*)      d_out;

    const int batch  = in_sizes[3];                 // item_ids count
    const int blocks = (batch + WARPS_PER_BLOCK - 1) / WARPS_PER_BLOCK;

    features_linear_kernel<<<blocks, THREADS>>>(
        fids, ratings, segs, item_ids, userW, ratingW, itemW, bias, out, batch);
}